// round 1
// baseline (speedup 1.0000x reference)
#include <cuda_runtime.h>
#include <cuda_bf16.h>
#include <math_constants.h>

// ---------------------------------------------------------------------------
// GATConv: N=100000 nodes (128 in-feats), E=1600000 edges (16 in-feats),
// H=4 heads, D=32 out per head.
// Pipeline:
//   K0  init: zero counters
//   K0b w_eh[k][h] = sum_d W_edge[k, h*32+d] * attn_edge[h,d]   (16x4)
//   K0c Wc = [W_fc | W_res]  (128 x 256)
//   K1  SGEMM: feat = X@W_fc ; out = X@W_res + bias
//   K2  a_src[n,h], a_dst[n,h] from feat
//   K3  histogram count[dst]
//   K4  exclusive scan -> offsets
//   K5  fill CSR edge ids by dst
//   K6  e[e,h] = leakyrelu(a_src[src]+a_dst[dst]+edge@w_eh)
//   K7  warp-per-node: online softmax over incoming edges + weighted gather
//       of feat[src], accumulate into out (no float atomics anywhere)
// ---------------------------------------------------------------------------

#define N_NODES 100000
#define N_EDGES 1600000
#define NEG_SLOPE 0.2f

__device__ float d_feat[N_NODES * 128];
__device__ float d_asrc[N_NODES * 4];
__device__ float d_adst[N_NODES * 4];
__device__ float d_ebuf[N_EDGES * 4];
__device__ float d_weh[64];            // [k=16][h=4]
__device__ float d_Wc[128 * 256];      // [K=128][N=256] = [W_fc | W_res]
__device__ int   d_count[N_NODES + 1];
__device__ int   d_count2[N_NODES];
__device__ int   d_offsets[N_NODES + 1];
__device__ int   d_csr[N_EDGES];

// ---------------- K0: zero counters ----------------
__global__ void k_init() {
    int i = blockIdx.x * blockDim.x + threadIdx.x;
    int total = (N_NODES + 1) + N_NODES;
    for (; i < total; i += gridDim.x * blockDim.x) {
        if (i <= N_NODES) d_count[i] = 0;
        else d_count2[i - (N_NODES + 1)] = 0;
    }
}

// ---------------- K0b: w_eh precompute ----------------
__global__ void k_weh(const float* __restrict__ W_edge,
                      const float* __restrict__ attn_edge) {
    int t = threadIdx.x;          // 64 threads
    if (t >= 64) return;
    int k = t >> 2;               // 0..15
    int h = t & 3;                // 0..3
    float s = 0.f;
    #pragma unroll
    for (int d = 0; d < 32; d++)
        s += W_edge[k * 128 + h * 32 + d] * attn_edge[h * 32 + d];
    d_weh[k * 4 + h] = s;
}

// ---------------- K0c: combined weight ----------------
__global__ void k_wc(const float* __restrict__ W_fc,
                     const float* __restrict__ W_res) {
    int i = blockIdx.x * blockDim.x + threadIdx.x;
    if (i >= 128 * 256) return;
    int k = i >> 8;        // row
    int c = i & 255;       // col
    d_Wc[i] = (c < 128) ? W_fc[k * 128 + c] : W_res[k * 128 + (c - 128)];
}

// ---------------- K1: SGEMM  C[M,256] = A[M,128] @ Wc[128,256] ----------------
// BM=128, BN=128, BK=8, 256 threads, 8x8 per thread
__global__ __launch_bounds__(256, 2)
void k_sgemm(const float* __restrict__ A, float* __restrict__ out,
             const float* __restrict__ bias, int M) {
    __shared__ float As[8][128];
    __shared__ float Bs[8][128];

    int tid = threadIdx.x;
    int row0 = blockIdx.x * 128;
    int col0 = blockIdx.y * 128;

    int tm = (tid / 16) * 8;
    int tn = (tid % 16) * 8;

    int a_row = tid >> 1;
    int a_col = (tid & 1) * 4;
    int b_row = tid >> 5;
    int b_col = (tid & 31) * 4;

    float acc[8][8];
    #pragma unroll
    for (int i = 0; i < 8; i++)
        #pragma unroll
        for (int j = 0; j < 8; j++) acc[i][j] = 0.f;

    for (int kk = 0; kk < 128; kk += 8) {
        // load A tile (guarded), transposed into As[k][m]
        float4 av = make_float4(0.f, 0.f, 0.f, 0.f);
        int grow = row0 + a_row;
        if (grow < M)
            av = *(const float4*)(A + (size_t)grow * 128 + kk + a_col);
        As[a_col + 0][a_row] = av.x;
        As[a_col + 1][a_row] = av.y;
        As[a_col + 2][a_row] = av.z;
        As[a_col + 3][a_row] = av.w;
        // load B tile
        float4 bv = *(const float4*)(d_Wc + (kk + b_row) * 256 + col0 + b_col);
        *(float4*)&Bs[b_row][b_col] = bv;
        __syncthreads();

        #pragma unroll
        for (int k = 0; k < 8; k++) {
            float ar[8], br[8];
            #pragma unroll
            for (int i = 0; i < 8; i++) ar[i] = As[k][tm + i];
            #pragma unroll
            for (int j = 0; j < 8; j++) br[j] = Bs[k][tn + j];
            #pragma unroll
            for (int i = 0; i < 8; i++)
                #pragma unroll
                for (int j = 0; j < 8; j++) acc[i][j] += ar[i] * br[j];
        }
        __syncthreads();
    }

    // epilogue: col<128 -> d_feat ; col>=128 -> out + bias
    #pragma unroll
    for (int i = 0; i < 8; i++) {
        int grow = row0 + tm + i;
        if (grow >= M) continue;
        #pragma unroll
        for (int j = 0; j < 8; j++) {
            int gcol = col0 + tn + j;
            float v = acc[i][j];
            if (gcol < 128) {
                d_feat[(size_t)grow * 128 + gcol] = v;
            } else {
                int oc = gcol - 128;
                out[(size_t)grow * 128 + oc] = v + bias[oc];
            }
        }
    }
}

// ---------------- K2: per-node attention logits (warp per node) ----------------
__global__ void k_attn_node(const float* __restrict__ attn_src,
                            const float* __restrict__ attn_dst) {
    int warp = (blockIdx.x * blockDim.x + threadIdx.x) >> 5;
    int lane = threadIdx.x & 31;
    if (warp >= N_NODES) return;
    int n = warp;

    float4 fv = *(const float4*)(d_feat + (size_t)n * 128 + lane * 4);
    float4 as = *(const float4*)(attn_src + lane * 4);
    float4 ad = *(const float4*)(attn_dst + lane * 4);

    float ps = fv.x * as.x + fv.y * as.y + fv.z * as.z + fv.w * as.w;
    float pd = fv.x * ad.x + fv.y * ad.y + fv.z * ad.z + fv.w * ad.w;

    // reduce within groups of 8 lanes (one head each)
    #pragma unroll
    for (int o = 1; o < 8; o <<= 1) {
        ps += __shfl_xor_sync(0xffffffffu, ps, o);
        pd += __shfl_xor_sync(0xffffffffu, pd, o);
    }
    if ((lane & 7) == 0) {
        int h = lane >> 3;
        d_asrc[n * 4 + h] = ps;
        d_adst[n * 4 + h] = pd;
    }
}

// ---------------- K3: histogram ----------------
__global__ void k_hist(const int* __restrict__ dst) {
    int i = blockIdx.x * blockDim.x + threadIdx.x;
    if (i < N_EDGES) atomicAdd(&d_count[dst[i]], 1);
}

// ---------------- K4: single-block exclusive scan ----------------
__global__ void k_scan() {
    __shared__ int warpsum[32];
    int tid = threadIdx.x;
    int lane = tid & 31, wid = tid >> 5;
    int running = 0;
    if (tid == 0) d_offsets[0] = 0;
    for (int base = 0; base < N_NODES; base += 1024) {
        int i = base + tid;
        int v = (i < N_NODES) ? d_count[i] : 0;
        int x = v;
        #pragma unroll
        for (int o = 1; o < 32; o <<= 1) {
            int t = __shfl_up_sync(0xffffffffu, x, o);
            if (lane >= o) x += t;
        }
        if (lane == 31) warpsum[wid] = x;
        __syncthreads();
        if (wid == 0) {
            int y = warpsum[lane];
            #pragma unroll
            for (int o = 1; o < 32; o <<= 1) {
                int t = __shfl_up_sync(0xffffffffu, y, o);
                if (lane >= o) y += t;
            }
            warpsum[lane] = y;
        }
        __syncthreads();
        int prefix = (wid > 0) ? warpsum[wid - 1] : 0;
        int incl = running + prefix + x;
        if (i < N_NODES) d_offsets[i + 1] = incl;
        int tile_total = warpsum[31];
        __syncthreads();
        running += tile_total;
    }
}

// ---------------- K5: fill CSR ----------------
__global__ void k_fill(const int* __restrict__ dst) {
    int i = blockIdx.x * blockDim.x + threadIdx.x;
    if (i >= N_EDGES) return;
    int d = dst[i];
    int p = d_offsets[d] + atomicAdd(&d_count2[d], 1);
    d_csr[p] = i;
}

// ---------------- K6: per-edge logits ----------------
__global__ void k_edge_e(const float* __restrict__ edge_inputs,
                         const int* __restrict__ src,
                         const int* __restrict__ dst) {
    __shared__ float sweh[64];
    if (threadIdx.x < 64) sweh[threadIdx.x] = d_weh[threadIdx.x];
    __syncthreads();

    int e = blockIdx.x * blockDim.x + threadIdx.x;
    if (e >= N_EDGES) return;

    int s = src[e];
    int d = dst[e];
    float4 as = *(const float4*)(d_asrc + s * 4);
    float4 ad = *(const float4*)(d_adst + d * 4);

    float ae[4] = {0.f, 0.f, 0.f, 0.f};
    const float* ep = edge_inputs + (size_t)e * 16;
    #pragma unroll
    for (int kq = 0; kq < 4; kq++) {
        float4 ev = *(const float4*)(ep + kq * 4);
        float efs[4] = {ev.x, ev.y, ev.z, ev.w};
        #pragma unroll
        for (int kk = 0; kk < 4; kk++) {
            int k = kq * 4 + kk;
            #pragma unroll
            for (int h = 0; h < 4; h++)
                ae[h] += efs[kk] * sweh[k * 4 + h];
        }
    }

    float av[4] = {as.x, as.y, as.z, as.w};
    float dv[4] = {ad.x, ad.y, ad.z, ad.w};
    float4 eo;
    float res[4];
    #pragma unroll
    for (int h = 0; h < 4; h++) {
        float v = av[h] + dv[h] + ae[h];
        res[h] = (v > 0.f) ? v : NEG_SLOPE * v;
    }
    eo.x = res[0]; eo.y = res[1]; eo.z = res[2]; eo.w = res[3];
    *(float4*)(d_ebuf + (size_t)e * 4) = eo;
}

// ---------------- K7: warp-per-node softmax + aggregate ----------------
#define NEG_BIG (-1.0e30f)
__global__ void k_aggregate(const int* __restrict__ src,
                            float* __restrict__ out) {
    int warp = (blockIdx.x * blockDim.x + threadIdx.x) >> 5;
    int lane = threadIdx.x & 31;
    if (warp >= N_NODES) return;
    int n = warp;

    int begin = d_offsets[n];
    int end = d_offsets[n + 1];
    int deg = end - begin;
    if (deg == 0) return;

    // ---- pass 1: online softmax stats per head ----
    float m[4] = {NEG_BIG, NEG_BIG, NEG_BIG, NEG_BIG};
    float s[4] = {0.f, 0.f, 0.f, 0.f};
    for (int j = lane; j < deg; j += 32) {
        int eid = d_csr[begin + j];
        float4 ev4 = *(const float4*)(d_ebuf + (size_t)eid * 4);
        float ev[4] = {ev4.x, ev4.y, ev4.z, ev4.w};
        #pragma unroll
        for (int h = 0; h < 4; h++) {
            float nm = fmaxf(m[h], ev[h]);
            s[h] = s[h] * __expf(m[h] - nm) + __expf(ev[h] - nm);
            m[h] = nm;
        }
    }
    // merge across lanes (butterfly -> all lanes hold final (m,s))
    #pragma unroll
    for (int o = 16; o > 0; o >>= 1) {
        #pragma unroll
        for (int h = 0; h < 4; h++) {
            float om = __shfl_xor_sync(0xffffffffu, m[h], o);
            float os = __shfl_xor_sync(0xffffffffu, s[h], o);
            float nm = fmaxf(m[h], om);
            s[h] = s[h] * __expf(m[h] - nm) + os * __expf(om - nm);
            m[h] = nm;
        }
    }

    // ---- pass 2: weighted gather of feat[src] ----
    int hl = lane >> 3;                 // this lane's head
    float mh = m[hl];
    float inv = 1.f / s[hl];

    float acc0 = 0.f, acc1 = 0.f, acc2 = 0.f, acc3 = 0.f;
    for (int j = 0; j < deg; j++) {
        int eid = d_csr[begin + j];          // broadcast across warp
        float eh = d_ebuf[(size_t)eid * 4 + hl];
        float w = __expf(eh - mh) * inv;
        int sn = src[eid];
        float4 fv = *(const float4*)(d_feat + (size_t)sn * 128 + lane * 4);
        acc0 += fv.x * w;
        acc1 += fv.y * w;
        acc2 += fv.z * w;
        acc3 += fv.w * w;
    }

    float4* op = (float4*)(out + (size_t)n * 128 + lane * 4);
    float4 ov = *op;                      // out already = res + bias
    ov.x += acc0; ov.y += acc1; ov.z += acc2; ov.w += acc3;
    *op = ov;
}

// ---------------------------------------------------------------------------
extern "C" void kernel_launch(void* const* d_in, const int* in_sizes, int n_in,
                              void* d_out, int out_size) {
    const float* node_inputs = (const float*)d_in[0];
    const float* edge_inputs = (const float*)d_in[1];
    const int*   src         = (const int*)d_in[2];
    const int*   dst         = (const int*)d_in[3];
    const float* W_fc        = (const float*)d_in[4];
    const float* attn_src_p  = (const float*)d_in[5];
    const float* attn_dst_p  = (const float*)d_in[6];
    const float* W_edge      = (const float*)d_in[7];
    const float* attn_edge_p = (const float*)d_in[8];
    const float* W_res       = (const float*)d_in[9];
    const float* bias_p      = (const float*)d_in[10];
    float* out = (float*)d_out;

    // K0: zero counters
    k_init<<<256, 256>>>();
    // K0b: w_eh
    k_weh<<<1, 64>>>(W_edge, attn_edge_p);
    // K0c: combined weights
    k_wc<<<(128 * 256 + 255) / 256, 256>>>(W_fc, W_res);
    // K1: SGEMM feat + residual(+bias)
    {
        dim3 grid((N_NODES + 127) / 128, 2);
        k_sgemm<<<grid, 256>>>(node_inputs, out, bias_p, N_NODES);
    }
    // K2: per-node attention logits
    k_attn_node<<<(N_NODES * 32 + 255) / 256, 256>>>(attn_src_p, attn_dst_p);
    // K3: histogram
    k_hist<<<(N_EDGES + 255) / 256, 256>>>(dst);
    // K4: scan
    k_scan<<<1, 1024>>>();
    // K5: CSR fill
    k_fill<<<(N_EDGES + 255) / 256, 256>>>(dst);
    // K6: edge logits
    k_edge_e<<<(N_EDGES + 255) / 256, 256>>>(edge_inputs, src, dst);
    // K7: aggregate
    k_aggregate<<<(N_NODES * 32 + 255) / 256, 256>>>(src, out);
}

// round 2
// speedup vs baseline: 1.1769x; 1.1769x over previous
#include <cuda_runtime.h>
#include <cuda_bf16.h>

// ---------------------------------------------------------------------------
// GATConv: N=100000 nodes (128 in), E=1600000 edges (16 in), H=4, D=32.
// Pipeline:
//   K0  zero counters
//   K0b w_eh[k][h] = sum_d W_edge[k,h*32+d]*attn_edge[h,d]
//   K0c Wc = [W_fc | W_res]
//   K1  f32x2 SGEMM: feat = X@W_fc ; out = X@W_res + bias
//   K2  a_src/a_dst per node
//   K3  histogram count[dst]       (int4 vectorized)
//   K4  exclusive scan -> offsets  (thread-coarsened x4)
//   K5  d_pos[e] = CSR slot (coalesced write only)
//   K6  e logits -> 32B payload {e4, src} scattered to CSR position
//   K7  warp-per-node: coalesced online softmax + broadcast gather-aggregate
// ---------------------------------------------------------------------------

#define N_NODES 100000
#define N_EDGES 1600000
#define NEG_SLOPE 0.2f
#define NEG_BIG (-1.0e30f)

struct __align__(32) Pay { float4 e; int s; int pad0, pad1, pad2; };

__device__ __align__(16) float d_feat[N_NODES * 128];
__device__ __align__(16) float d_asrc[N_NODES * 4];
__device__ __align__(16) float d_adst[N_NODES * 4];
__device__ Pay   d_pay[N_EDGES];
__device__ __align__(16) float d_weh[64];            // [k=16][h=4]
__device__ __align__(16) float d_Wc[128 * 256];      // [W_fc | W_res]
__device__ __align__(16) int   d_count[N_NODES + 4];
__device__ __align__(16) int   d_count2[N_NODES];
__device__ __align__(16) int   d_offsets[N_NODES + 1];
__device__ __align__(16) int   d_pos[N_EDGES];

// ---------------- f32x2 helpers ----------------
__device__ __forceinline__ unsigned long long fma_x2(unsigned long long a,
                                                     unsigned long long b,
                                                     unsigned long long c) {
    unsigned long long d;
    asm("fma.rn.f32x2 %0, %1, %2, %3;" : "=l"(d) : "l"(a), "l"(b), "l"(c));
    return d;
}
__device__ __forceinline__ unsigned long long dup_x2(float x) {
    unsigned long long d;
    asm("mov.b64 %0, {%1, %1};" : "=l"(d) : "f"(x));
    return d;
}
__device__ __forceinline__ void unpack_x2(float& lo, float& hi, unsigned long long v) {
    asm("mov.b64 {%0, %1}, %2;" : "=f"(lo), "=f"(hi) : "l"(v));
}

// ---------------- K0: zero counters ----------------
__global__ void k_init() {
    int i = blockIdx.x * blockDim.x + threadIdx.x;
    int total = (N_NODES + 4) + N_NODES;
    for (; i < total; i += gridDim.x * blockDim.x) {
        if (i < N_NODES + 4) d_count[i] = 0;
        else d_count2[i - (N_NODES + 4)] = 0;
    }
}

// ---------------- K0b: w_eh precompute ----------------
__global__ void k_weh(const float* __restrict__ W_edge,
                      const float* __restrict__ attn_edge) {
    int t = threadIdx.x;
    if (t >= 64) return;
    int k = t >> 2, h = t & 3;
    float s = 0.f;
    #pragma unroll
    for (int d = 0; d < 32; d++)
        s += W_edge[k * 128 + h * 32 + d] * attn_edge[h * 32 + d];
    d_weh[k * 4 + h] = s;
}

// ---------------- K0c: combined weight ----------------
__global__ void k_wc(const float* __restrict__ W_fc,
                     const float* __restrict__ W_res) {
    int i = blockIdx.x * blockDim.x + threadIdx.x;
    if (i >= 128 * 256) return;
    int k = i >> 8, c = i & 255;
    d_Wc[i] = (c < 128) ? W_fc[k * 128 + c] : W_res[k * 128 + (c - 128)];
}

// ---------------- K1: f32x2 SGEMM C[M,256] = A[M,128] @ Wc ----------------
// BM=128, BN=128, BK=8, 256 threads, 8x8 per thread, packed-pair FMA
__global__ __launch_bounds__(256, 2)
void k_sgemm(const float* __restrict__ A, float* __restrict__ out,
             const float* __restrict__ bias, int M) {
    __shared__ __align__(16) float As[8][128];
    __shared__ __align__(16) float Bs[8][128];

    int tid = threadIdx.x;
    int row0 = blockIdx.x * 128;
    int col0 = blockIdx.y * 128;

    int tm = (tid / 16) * 8;
    int tn = (tid % 16) * 8;

    int a_row = tid >> 1;
    int a_col = (tid & 1) * 4;
    int b_row = tid >> 5;
    int b_col = (tid & 31) * 4;

    unsigned long long acc[8][4];
    #pragma unroll
    for (int i = 0; i < 8; i++)
        #pragma unroll
        for (int jp = 0; jp < 4; jp++) acc[i][jp] = 0ull;

    for (int kk = 0; kk < 128; kk += 8) {
        float4 av = make_float4(0.f, 0.f, 0.f, 0.f);
        int grow = row0 + a_row;
        if (grow < M)
            av = *(const float4*)(A + (size_t)grow * 128 + kk + a_col);
        As[a_col + 0][a_row] = av.x;
        As[a_col + 1][a_row] = av.y;
        As[a_col + 2][a_row] = av.z;
        As[a_col + 3][a_row] = av.w;
        float4 bv = *(const float4*)(d_Wc + (kk + b_row) * 256 + col0 + b_col);
        *(float4*)&Bs[b_row][b_col] = bv;
        __syncthreads();

        #pragma unroll
        for (int k = 0; k < 8; k++) {
            float4 a0 = *(const float4*)&As[k][tm];
            float4 a1 = *(const float4*)&As[k][tm + 4];
            ulonglong2 b0 = *(const ulonglong2*)&Bs[k][tn];
            ulonglong2 b1 = *(const ulonglong2*)&Bs[k][tn + 4];
            unsigned long long bp[4] = {b0.x, b0.y, b1.x, b1.y};
            float af[8] = {a0.x, a0.y, a0.z, a0.w, a1.x, a1.y, a1.z, a1.w};
            #pragma unroll
            for (int i = 0; i < 8; i++) {
                unsigned long long ad = dup_x2(af[i]);
                #pragma unroll
                for (int jp = 0; jp < 4; jp++)
                    acc[i][jp] = fma_x2(ad, bp[jp], acc[i][jp]);
            }
        }
        __syncthreads();
    }

    // unpack to scalars
    float c[8][8];
    #pragma unroll
    for (int i = 0; i < 8; i++)
        #pragma unroll
        for (int jp = 0; jp < 4; jp++)
            unpack_x2(c[i][jp * 2], c[i][jp * 2 + 1], acc[i][jp]);

    if (col0 == 0) {  // feat columns (0..127)
        #pragma unroll
        for (int i = 0; i < 8; i++) {
            int grow = row0 + tm + i;
            if (grow >= M) continue;
            float* fp = d_feat + (size_t)grow * 128 + tn;
            *(float4*)fp = make_float4(c[i][0], c[i][1], c[i][2], c[i][3]);
            *(float4*)(fp + 4) = make_float4(c[i][4], c[i][5], c[i][6], c[i][7]);
        }
    } else {          // residual columns (128..255) -> out + bias
        float4 bz0 = *(const float4*)(bias + tn);
        float4 bz1 = *(const float4*)(bias + tn + 4);
        #pragma unroll
        for (int i = 0; i < 8; i++) {
            int grow = row0 + tm + i;
            if (grow >= M) continue;
            float* op = out + (size_t)grow * 128 + tn;
            *(float4*)op = make_float4(c[i][0] + bz0.x, c[i][1] + bz0.y,
                                       c[i][2] + bz0.z, c[i][3] + bz0.w);
            *(float4*)(op + 4) = make_float4(c[i][4] + bz1.x, c[i][5] + bz1.y,
                                             c[i][6] + bz1.z, c[i][7] + bz1.w);
        }
    }
}

// ---------------- K2: per-node attention logits (warp per node) ----------------
__global__ void k_attn_node(const float* __restrict__ attn_src,
                            const float* __restrict__ attn_dst) {
    int warp = (blockIdx.x * blockDim.x + threadIdx.x) >> 5;
    int lane = threadIdx.x & 31;
    if (warp >= N_NODES) return;
    int n = warp;

    float4 fv = *(const float4*)(d_feat + (size_t)n * 128 + lane * 4);
    float4 as = *(const float4*)(attn_src + lane * 4);
    float4 ad = *(const float4*)(attn_dst + lane * 4);

    float ps = fv.x * as.x + fv.y * as.y + fv.z * as.z + fv.w * as.w;
    float pd = fv.x * ad.x + fv.y * ad.y + fv.z * ad.z + fv.w * ad.w;

    #pragma unroll
    for (int o = 1; o < 8; o <<= 1) {
        ps += __shfl_xor_sync(0xffffffffu, ps, o);
        pd += __shfl_xor_sync(0xffffffffu, pd, o);
    }
    if ((lane & 7) == 0) {
        int h = lane >> 3;
        d_asrc[n * 4 + h] = ps;
        d_adst[n * 4 + h] = pd;
    }
}

// ---------------- K3: histogram (vectorized) ----------------
__global__ void k_hist(const int* __restrict__ dst) {
    int i4 = (blockIdx.x * blockDim.x + threadIdx.x) * 4;
    if (i4 + 3 < N_EDGES) {
        int4 d = *(const int4*)(dst + i4);
        atomicAdd(&d_count[d.x], 1);
        atomicAdd(&d_count[d.y], 1);
        atomicAdd(&d_count[d.z], 1);
        atomicAdd(&d_count[d.w], 1);
    } else {
        for (int i = i4; i < N_EDGES; i++) atomicAdd(&d_count[dst[i]], 1);
    }
}

// ---------------- K4: single-block exclusive scan, x4 coarsened ----------------
__global__ void k_scan() {
    __shared__ int wsum[32];
    int tid = threadIdx.x;
    int lane = tid & 31, wid = tid >> 5;
    int running = 0;
    if (tid == 0) d_offsets[0] = 0;
    for (int base = 0; base < N_NODES; base += 4096) {
        int i0 = base + tid * 4;
        int v0 = 0, v1 = 0, v2 = 0, v3 = 0;
        if (i0 + 3 < N_NODES) {
            int4 v = *(const int4*)&d_count[i0];
            v0 = v.x; v1 = v.y; v2 = v.z; v3 = v.w;
        } else {
            if (i0 + 0 < N_NODES) v0 = d_count[i0 + 0];
            if (i0 + 1 < N_NODES) v1 = d_count[i0 + 1];
            if (i0 + 2 < N_NODES) v2 = d_count[i0 + 2];
            if (i0 + 3 < N_NODES) v3 = d_count[i0 + 3];
        }
        int p0 = v0, p1 = p0 + v1, p2 = p1 + v2, p3 = p2 + v3;
        int x = p3;
        #pragma unroll
        for (int o = 1; o < 32; o <<= 1) {
            int t = __shfl_up_sync(0xffffffffu, x, o);
            if (lane >= o) x += t;
        }
        if (lane == 31) wsum[wid] = x;
        __syncthreads();
        if (wid == 0) {
            int y = wsum[lane];
            #pragma unroll
            for (int o = 1; o < 32; o <<= 1) {
                int t = __shfl_up_sync(0xffffffffu, y, o);
                if (lane >= o) y += t;
            }
            wsum[lane] = y;
        }
        __syncthreads();
        int warpoff = (wid > 0) ? wsum[wid - 1] : 0;
        int texcl = x - p3;
        int bs = running + warpoff + texcl;
        if (i0 + 0 < N_NODES) d_offsets[i0 + 1] = bs + p0;
        if (i0 + 1 < N_NODES) d_offsets[i0 + 2] = bs + p1;
        if (i0 + 2 < N_NODES) d_offsets[i0 + 3] = bs + p2;
        if (i0 + 3 < N_NODES) d_offsets[i0 + 4] = bs + p3;
        int tot = wsum[31];
        __syncthreads();
        running += tot;
    }
}

// ---------------- K5: CSR positions (coalesced write) ----------------
__global__ void k_fill(const int* __restrict__ dst) {
    int i = blockIdx.x * blockDim.x + threadIdx.x;
    if (i >= N_EDGES) return;
    int d = dst[i];
    int p = d_offsets[d] + atomicAdd(&d_count2[d], 1);
    d_pos[i] = p;
}

// ---------------- K6: per-edge logits -> CSR-ordered payload ----------------
__global__ void k_edge_e(const float* __restrict__ edge_inputs,
                         const int* __restrict__ src,
                         const int* __restrict__ dst) {
    __shared__ float sweh[64];
    if (threadIdx.x < 64) sweh[threadIdx.x] = d_weh[threadIdx.x];
    __syncthreads();

    int e = blockIdx.x * blockDim.x + threadIdx.x;
    if (e >= N_EDGES) return;

    int s = src[e];
    int d = dst[e];
    float4 as = *(const float4*)(d_asrc + s * 4);
    float4 ad = *(const float4*)(d_adst + d * 4);

    float ae[4] = {0.f, 0.f, 0.f, 0.f};
    const float* ep = edge_inputs + (size_t)e * 16;
    #pragma unroll
    for (int kq = 0; kq < 4; kq++) {
        float4 ev = *(const float4*)(ep + kq * 4);
        float efs[4] = {ev.x, ev.y, ev.z, ev.w};
        #pragma unroll
        for (int kk = 0; kk < 4; kk++) {
            int k = kq * 4 + kk;
            #pragma unroll
            for (int h = 0; h < 4; h++)
                ae[h] += efs[kk] * sweh[k * 4 + h];
        }
    }

    float av[4] = {as.x, as.y, as.z, as.w};
    float dv[4] = {ad.x, ad.y, ad.z, ad.w};
    float res[4];
    #pragma unroll
    for (int h = 0; h < 4; h++) {
        float v = av[h] + dv[h] + ae[h];
        res[h] = (v > 0.f) ? v : NEG_SLOPE * v;
    }

    int p = d_pos[e];
    char* pp = (char*)(d_pay + p);
    *(float4*)pp = make_float4(res[0], res[1], res[2], res[3]);
    *(int4*)(pp + 16) = make_int4(s, 0, 0, 0);
}

// ---------------- K7: warp-per-node softmax + aggregate ----------------
__global__ void k_aggregate(float* __restrict__ out) {
    int warp = (blockIdx.x * blockDim.x + threadIdx.x) >> 5;
    int lane = threadIdx.x & 31;
    if (warp >= N_NODES) return;
    int n = warp;

    int begin = d_offsets[n];
    int deg = d_offsets[n + 1] - begin;
    if (deg == 0) return;

    // ---- pass 1: online softmax stats per head (coalesced stream) ----
    float m[4] = {NEG_BIG, NEG_BIG, NEG_BIG, NEG_BIG};
    float s[4] = {0.f, 0.f, 0.f, 0.f};
    for (int j = lane; j < deg; j += 32) {
        float4 ev4 = *(const float4*)(d_pay + (begin + j));
        float ev[4] = {ev4.x, ev4.y, ev4.z, ev4.w};
        #pragma unroll
        for (int h = 0; h < 4; h++) {
            float nm = fmaxf(m[h], ev[h]);
            s[h] = s[h] * __expf(m[h] - nm) + __expf(ev[h] - nm);
            m[h] = nm;
        }
    }
    #pragma unroll
    for (int o = 16; o > 0; o >>= 1) {
        #pragma unroll
        for (int h = 0; h < 4; h++) {
            float om = __shfl_xor_sync(0xffffffffu, m[h], o);
            float os = __shfl_xor_sync(0xffffffffu, s[h], o);
            float nm = fmaxf(m[h], om);
            s[h] = s[h] * __expf(m[h] - nm) + os * __expf(om - nm);
            m[h] = nm;
        }
    }
    float inv[4];
    #pragma unroll
    for (int h = 0; h < 4; h++) inv[h] = 1.f / s[h];

    int hl = lane >> 3;

    // ---- pass 2: chunked broadcast + independent feat gathers ----
    float acc0 = 0.f, acc1 = 0.f, acc2 = 0.f, acc3 = 0.f;
    for (int base = 0; base < deg; base += 32) {
        int j = base + lane;
        float4 w4 = make_float4(0.f, 0.f, 0.f, 0.f);
        int sn = 0;
        if (j < deg) {
            const char* pp = (const char*)(d_pay + (begin + j));
            float4 ev = *(const float4*)pp;
            sn = *(const int*)(pp + 16);
            w4.x = __expf(ev.x - m[0]) * inv[0];
            w4.y = __expf(ev.y - m[1]) * inv[1];
            w4.z = __expf(ev.z - m[2]) * inv[2];
            w4.w = __expf(ev.w - m[3]) * inv[3];
        }
        int cnt = min(32, deg - base);
        #pragma unroll 4
        for (int k = 0; k < cnt; k++) {
            float wx = __shfl_sync(0xffffffffu, w4.x, k);
            float wy = __shfl_sync(0xffffffffu, w4.y, k);
            float wz = __shfl_sync(0xffffffffu, w4.z, k);
            float ww = __shfl_sync(0xffffffffu, w4.w, k);
            int snk = __shfl_sync(0xffffffffu, sn, k);
            float w = (hl < 2) ? (hl == 0 ? wx : wy) : (hl == 2 ? wz : ww);
            float4 fv = *(const float4*)(d_feat + (size_t)snk * 128 + lane * 4);
            acc0 += fv.x * w;
            acc1 += fv.y * w;
            acc2 += fv.z * w;
            acc3 += fv.w * w;
        }
    }

    float4* op = (float4*)(out + (size_t)n * 128 + lane * 4);
    float4 ov = *op;  // out already = residual + bias
    ov.x += acc0; ov.y += acc1; ov.z += acc2; ov.w += acc3;
    *op = ov;
}

// ---------------------------------------------------------------------------
extern "C" void kernel_launch(void* const* d_in, const int* in_sizes, int n_in,
                              void* d_out, int out_size) {
    const float* node_inputs = (const float*)d_in[0];
    const float* edge_inputs = (const float*)d_in[1];
    const int*   src         = (const int*)d_in[2];
    const int*   dst         = (const int*)d_in[3];
    const float* W_fc        = (const float*)d_in[4];
    const float* attn_src_p  = (const float*)d_in[5];
    const float* attn_dst_p  = (const float*)d_in[6];
    const float* W_edge      = (const float*)d_in[7];
    const float* attn_edge_p = (const float*)d_in[8];
    const float* W_res       = (const float*)d_in[9];
    const float* bias_p      = (const float*)d_in[10];
    float* out = (float*)d_out;

    k_init<<<256, 256>>>();
    k_weh<<<1, 64>>>(W_edge, attn_edge_p);
    k_wc<<<(128 * 256 + 255) / 256, 256>>>(W_fc, W_res);
    {
        dim3 grid((N_NODES + 127) / 128, 2);
        k_sgemm<<<grid, 256>>>(node_inputs, out, bias_p, N_NODES);
    }
    k_attn_node<<<(N_NODES * 32 + 255) / 256, 256>>>(attn_src_p, attn_dst_p);
    k_hist<<<(N_EDGES / 4 + 255) / 256, 256>>>(dst);
    k_scan<<<1, 1024>>>();
    k_fill<<<(N_EDGES + 255) / 256, 256>>>(dst);
    k_edge_e<<<(N_EDGES + 255) / 256, 256>>>(edge_inputs, src, dst);
    k_aggregate<<<(N_NODES * 32 + 255) / 256, 256>>>(src ? out : out);
}